// round 15
// baseline (speedup 1.0000x reference)
#include <cuda_runtime.h>
#include <cuda_fp16.h>

// MyModel_83597243450144 : 4-layer LSTM autoencoder, tensor-core split-fp16.
// B=2048, T=128, H1=128, H2=64. Gates i,f,g,o; g relu, h = o*relu(c).
// z = hi@Whi + hi@Wlo + lo@Whi via mma.sync.m16n8k16 (f16 in, f32 acc).
//
// R15: cluster-of-2 N-split. Each CTA of a 2-CTA cluster computes half the
// units of every layer -> reads half the weights -> chip L2 traffic halves.
// h exchanged via DSMEM (st.shared::cluster) + mbarrier handshake, h buffers
// double-buffered by step parity. Within-CTA K-split (2-way / 4-way) with
// pbuf reduction keeps per-warp mma chains short.

#define B_ALL 2048
#define T_SEQ 128
#define BT 16
#define NCTAS 256            // 128 clusters of 2
#define RS1 136              // h row stride (halves) H=128 (128+8)
#define RS2 72               // H=64 (64+8)

typedef unsigned int uint;

// ---- device scratch ----
__device__ uint4 g_wfrag[57344];
__device__ float g_h2last[B_ALL * 64];

#define SEC_L1 0
#define SEC_L2 16384
#define SEC_L3 28672
#define SEC_L4 32768

// ---- smem layouts (dynamic) ----
// Phase A
#define A_H1HI 0       // [2][16*RS1] halves, parity stride 4352 B
#define A_H1LO 8704
#define A_H2HI 17408   // parity stride 2304 B
#define A_H2LO 22016
#define A_XS   26624   // float[16][132]
#define A_PBUF 35072   // 24576 B
#define A_MBH1 59648
#define A_MBH2 59656
#define SMEMA_BYTES 59680
// Phase B
#define B_H3HI 0       // parity stride 2304
#define B_H3LO 4608
#define B_H4HI 9216    // parity stride 4352
#define B_H4LO 17920
#define B_H2S  26624   // float[16][66]
#define B_PBUF 30848   // 24576
#define B_PD   55424   // float[128]
#define B_PD2  55936   // float[16]
#define B_MBH3 56000
#define B_MBH4 56008
#define B_MBD  56016
#define SMEMB_BYTES 56032

__device__ __forceinline__ float sigmoidf_(float v) {
    float r, h = 0.5f * v;
    asm("tanh.approx.f32 %0, %1;" : "=f"(r) : "f"(h));
    return fmaf(0.5f, r, 0.5f);
}
__device__ __forceinline__ uint packh_(__half lo, __half hi) {
    return (uint)__half_as_ushort(lo) | ((uint)__half_as_ushort(hi) << 16);
}
__device__ __forceinline__ uint ldh2_(const __half* p) { return *(const uint*)p; }
__device__ __forceinline__ void mma16816(float* c, uint a0, uint a1, uint a2,
                                         uint a3, uint b0, uint b1) {
    asm("mma.sync.aligned.m16n8k16.row.col.f32.f16.f16.f32 "
        "{%0,%1,%2,%3}, {%4,%5,%6,%7}, {%8,%9}, {%0,%1,%2,%3};"
        : "+f"(c[0]), "+f"(c[1]), "+f"(c[2]), "+f"(c[3])
        : "r"(a0), "r"(a1), "r"(a2), "r"(a3), "r"(b0), "r"(b1));
}
__device__ __forceinline__ float lstm_cell(float zi, float zf, float zg,
                                           float zo, float& c) {
    float iv = sigmoidf_(zi), fv = sigmoidf_(zf);
    float gv = fmaxf(zg, 0.0f), ov = sigmoidf_(zo);
    c = fmaf(fv, c, iv * gv);
    return ov * fmaxf(c, 0.0f);
}
__device__ __forceinline__ uint sm32_(const void* p) {
    uint r;
    asm("{.reg .u64 t; cvta.to.shared.u64 t, %1; cvt.u32.u64 %0, t;}"
        : "=r"(r) : "l"(p));
    return r;
}
__device__ __forceinline__ void mbar_init_(uint a, uint n) {
    asm volatile("mbarrier.init.shared.b64 [%0], %1;" :: "r"(a), "r"(n) : "memory");
}
__device__ __forceinline__ void arrive_rem_(uint remote_addr) {
    asm volatile("mbarrier.arrive.release.cluster.shared::cluster.b64 _, [%0];"
                 :: "r"(remote_addr) : "memory");
}
__device__ __forceinline__ void waitp_(uint mbar, uint par) {
    uint done = 0;
    while (!done) {
        asm volatile(
            "{\n\t.reg .pred p;\n\t"
            "mbarrier.try_wait.parity.acquire.cluster.shared::cta.b64 p, [%1], %2, 0x989680;\n\t"
            "selp.b32 %0, 1, 0, p;\n\t}"
            : "=r"(done) : "r"(mbar), "r"(par) : "memory");
    }
}
__device__ __forceinline__ void st16_rem_(uint addr, __half v) {
    asm volatile("st.shared::cluster.u16 [%0], %1;"
                 :: "r"(addr), "h"((unsigned short)__half_as_ushort(v)) : "memory");
}
__device__ __forceinline__ void st32_rem_(uint addr, float v) {
    asm volatile("st.shared::cluster.b32 [%0], %1;"
                 :: "r"(addr), "r"(__float_as_uint(v)) : "memory");
}
#define CLUSTER_SYNC_() do { \
    asm volatile("barrier.cluster.arrive.aligned;" ::: "memory"); \
    asm volatile("barrier.cluster.wait.aligned;" ::: "memory"); } while (0)

// GEMM partial: NKB k-blocks; weights kb0..kb0+NKB-1 of KBTOT-block section.
// A cols kk*16.. relative to (bhi,blo). nb = gg*nb_gs + nb_w.
template <int NKB, int KBTOT>
__device__ __forceinline__ void gemm_part(float (*C)[4], const uint4* wsec,
                                          int kb0, int nb_w, int nb_gs,
                                          const __half* bhi, const __half* blo,
                                          int rs, int g, int t) {
    const uint4* wl_ = wsec + (threadIdx.x & 31);
#pragma unroll
    for (int kk = 0; kk < NKB; kk++) {
        const int kb = kb0 + kk;
        const int c0 = kk * 16 + 2 * t;
        uint a0 = ldh2_(bhi + g * rs + c0);
        uint a1 = ldh2_(bhi + (g + 8) * rs + c0);
        uint a2 = ldh2_(bhi + g * rs + c0 + 8);
        uint a3 = ldh2_(bhi + (g + 8) * rs + c0 + 8);
        uint l0 = ldh2_(blo + g * rs + c0);
        uint l1 = ldh2_(blo + (g + 8) * rs + c0);
        uint l2 = ldh2_(blo + g * rs + c0 + 8);
        uint l3 = ldh2_(blo + (g + 8) * rs + c0 + 8);
#pragma unroll
        for (int gg = 0; gg < 4; gg++) {
            int nb = gg * nb_gs + nb_w;
            uint4 wf = wl_[(nb * KBTOT + kb) * 32];
            float* c = C[gg];
            mma16816(c, a0, a1, a2, a3, wf.x, wf.y);
            mma16816(c, a0, a1, a2, a3, wf.z, wf.w);
            mma16816(c, l0, l1, l2, l3, wf.x, wf.y);
        }
    }
}

// ---------------------------------------------------------------------------
__global__ void pack_kernel(const float* __restrict__ U1,
                            const float* __restrict__ W2, const float* __restrict__ U2,
                            const float* __restrict__ U3,
                            const float* __restrict__ W4, const float* __restrict__ U4) {
    int e = blockIdx.x * 256 + threadIdx.x;
    if (e >= 57344) return;
    int sec, KB, idx;
    if (e < 16384)      { sec = 0; KB = 8;  idx = e; }
    else if (e < 28672) { sec = 1; KB = 12; idx = e - 16384; }
    else if (e < 32768) { sec = 2; KB = 4;  idx = e - 28672; }
    else                { sec = 3; KB = 12; idx = e - 32768; }
    int lane = idx & 31, rest = idx >> 5;
    int kb = rest % KB, nb = rest / KB;
    int g = lane >> 2, t = lane & 3;
    int n = nb * 8 + g;
    __half h[4], l[4];
#pragma unroll
    for (int r = 0; r < 4; r++) {
        int k = kb * 16 + 2 * t + (r & 1) + (r >> 1) * 8;
        float v;
        if (sec == 0)      v = U1[k * 512 + n];
        else if (sec == 1) v = (k < 128) ? W2[k * 256 + n] : U2[(k - 128) * 256 + n];
        else if (sec == 2) v = U3[k * 256 + n];
        else               v = (k < 64) ? W4[k * 512 + n] : U4[(k - 64) * 512 + n];
        h[r] = __float2half_rn(v);
        l[r] = __float2half_rn(v - __half2float(h[r]));
    }
    uint4 o;
    o.x = packh_(h[0], h[1]);
    o.y = packh_(h[2], h[3]);
    o.z = packh_(l[0], l[1]);
    o.w = packh_(l[2], l[3]);
    g_wfrag[e] = o;
}

// ---------------------------------------------------------------------------
// Phase A: LSTM1 + LSTM2. 512 thr/CTA, cluster 2, 16 samples per cluster.
// ---------------------------------------------------------------------------
__global__ void __launch_bounds__(512, 1) __cluster_dims__(2, 1, 1)
phaseA_kernel(const float* __restrict__ x, const float* __restrict__ W1,
              const float* __restrict__ b1, const float* __restrict__ b2) {
    extern __shared__ char smem[];
    const int tid = threadIdx.x;
    const int w = tid >> 5, lane = tid & 31, g = lane >> 2, t = lane & 3;
    const int wl = w & 7, kh = w >> 3;    // L1: unit slice / K half
    const int wl2 = w & 3, kh2 = w >> 2;  // L2: unit slice / K quarter
    uint rk;
    asm("mov.u32 %0, %%cluster_ctarank;" : "=r"(rk));
    const uint peer = 1u - rk;
    const int b0 = (blockIdx.x >> 1) * BT;

    float* xs = (float*)(smem + A_XS);
    float* pb = (float*)(smem + A_PBUF);
    const uint sbase = sm32_(smem);
    uint rbase;
    asm("mapa.shared::cluster.u32 %0, %1, %2;" : "=r"(rbase) : "r"(sbase), "r"(peer));

    for (int i = tid; i < BT * T_SEQ; i += 512) {
        int b = i >> 7, s = i & 127;
        xs[b * 132 + s] = x[(b0 + b) * T_SEQ + s];
    }
    for (int i = tid; i < 6656; i += 512) ((uint*)smem)[i] = 0u;  // h buffers
    if (tid == 0) {
        mbar_init_(sbase + A_MBH1, 256);
        mbar_init_(sbase + A_MBH2, 128);
    }
    __syncthreads();
    CLUSTER_SYNC_();

    const int uL1 = 64 * (int)rk + 8 * wl + 2 * t;
    const int uL2 = 32 * (int)rk + 8 * wl2 + 2 * t;

    float b1v[8], w1v[8], b2v[8];
#pragma unroll
    for (int gg = 0; gg < 4; gg++)
#pragma unroll
        for (int e1 = 0; e1 < 2; e1++) {
            int col = gg * 128 + uL1 + e1;
            b1v[gg * 2 + e1] = b1[col];
            w1v[gg * 2 + e1] = W1[col];
            b2v[gg * 2 + e1] = b2[gg * 64 + uL2 + e1];
        }
    float c1[4], c2[4];
#pragma unroll
    for (int j = 0; j < 4; j++) { c1[j] = 0.0f; c2[j] = 0.0f; }

    for (int tt = 0; tt < T_SEQ; tt++) {
        const int pw = tt & 1, po = pw ^ 1;
        __half* h1hiR = (__half*)(smem + A_H1HI + po * 4352);
        __half* h1loR = (__half*)(smem + A_H1LO + po * 4352);
        __half* h1hiW = (__half*)(smem + A_H1HI + pw * 4352);
        __half* h1loW = (__half*)(smem + A_H1LO + pw * 4352);
        __half* h2hiR = (__half*)(smem + A_H2HI + po * 2304);
        __half* h2loR = (__half*)(smem + A_H2LO + po * 2304);
        __half* h2hiW = (__half*)(smem + A_H2HI + pw * 2304);
        __half* h2loW = (__half*)(smem + A_H2LO + pw * 2304);

        if (tt > 0) waitp_(sbase + A_MBH2, (tt - 1) & 1);  // peer h2(t-1)

        // ---- L1: z1 = x*W1 + h1(t-1)@U1 + b1 (K=128 split 64/64) ----
        float C1[4][4];
        if (kh == 0) {
            float xv0 = xs[g * 132 + tt], xv1 = xs[(g + 8) * 132 + tt];
#pragma unroll
            for (int gg = 0; gg < 4; gg++)
#pragma unroll
                for (int e = 0; e < 4; e++) {
                    int idx = gg * 2 + (e & 1);
                    C1[gg][e] = fmaf((e & 2) ? xv1 : xv0, w1v[idx], b1v[idx]);
                }
            gemm_part<4, 8>(C1, g_wfrag + SEC_L1, 0, 8 * rk + wl, 16,
                            h1hiR, h1loR, RS1, g, t);
        } else {
#pragma unroll
            for (int gg = 0; gg < 4; gg++)
#pragma unroll
                for (int e = 0; e < 4; e++) C1[gg][e] = 0.0f;
            gemm_part<4, 8>(C1, g_wfrag + SEC_L1, 4, 8 * rk + wl, 16,
                            h1hiR + 64, h1loR + 64, RS1, g, t);
#pragma unroll
            for (int gg = 0; gg < 4; gg++)
#pragma unroll
                for (int e = 0; e < 4; e++)
                    pb[(gg * 4 + e) * 256 + wl * 32 + lane] = C1[gg][e];
        }
        __syncthreads();
        if (kh == 0) {
#pragma unroll
            for (int e = 0; e < 4; e++) {
                int pi = wl * 32 + lane;
                float zi = C1[0][e] + pb[(0 + e) * 256 + pi];
                float zf = C1[1][e] + pb[(4 + e) * 256 + pi];
                float zg = C1[2][e] + pb[(8 + e) * 256 + pi];
                float zo = C1[3][e] + pb[(12 + e) * 256 + pi];
                float h = lstm_cell(zi, zf, zg, zo, c1[e]);
                int u = uL1 + (e & 1), s = g + ((e & 2) ? 8 : 0);
                int idx = s * RS1 + u;
                __half hh = __float2half_rn(h);
                __half hl = __float2half_rn(h - __half2float(hh));
                h1hiW[idx] = hh;
                h1loW[idx] = hl;
                st16_rem_(rbase + A_H1HI + pw * 4352 + idx * 2, hh);
                st16_rem_(rbase + A_H1LO + pw * 4352 + idx * 2, hl);
            }
            arrive_rem_(rbase + A_MBH1);
        }
        __syncthreads();
        waitp_(sbase + A_MBH1, tt & 1);  // peer h1(t)

        // ---- L2: z2 = h1(t)@W2 + h2(t-1)@U2 + b2 (K=192 split 48x4) ----
        float C2[4][4];
        if (kh2 == 0) {
#pragma unroll
            for (int gg = 0; gg < 4; gg++)
#pragma unroll
                for (int e = 0; e < 4; e++) C2[gg][e] = b2v[gg * 2 + (e & 1)];
            gemm_part<3, 12>(C2, g_wfrag + SEC_L2, 0, 4 * rk + wl2, 8,
                             h1hiW, h1loW, RS1, g, t);
        } else {
#pragma unroll
            for (int gg = 0; gg < 4; gg++)
#pragma unroll
                for (int e = 0; e < 4; e++) C2[gg][e] = 0.0f;
            if (kh2 == 1) {
                gemm_part<3, 12>(C2, g_wfrag + SEC_L2, 3, 4 * rk + wl2, 8,
                                 h1hiW + 48, h1loW + 48, RS1, g, t);
            } else if (kh2 == 2) {
                gemm_part<2, 12>(C2, g_wfrag + SEC_L2, 6, 4 * rk + wl2, 8,
                                 h1hiW + 96, h1loW + 96, RS1, g, t);
                gemm_part<1, 12>(C2, g_wfrag + SEC_L2, 8, 4 * rk + wl2, 8,
                                 h2hiR, h2loR, RS2, g, t);
            } else {
                gemm_part<3, 12>(C2, g_wfrag + SEC_L2, 9, 4 * rk + wl2, 8,
                                 h2hiR + 16, h2loR + 16, RS2, g, t);
            }
#pragma unroll
            for (int gg = 0; gg < 4; gg++)
#pragma unroll
                for (int e = 0; e < 4; e++)
                    pb[(kh2 - 1) * 2048 + (gg * 4 + e) * 128 + wl2 * 32 + lane] = C2[gg][e];
        }
        __syncthreads();
        if (kh2 == 0) {
#pragma unroll
            for (int e = 0; e < 4; e++) {
                int pi = wl2 * 32 + lane;
                float zi = C2[0][e], zf = C2[1][e], zg = C2[2][e], zo = C2[3][e];
#pragma unroll
                for (int q = 0; q < 3; q++) {
                    zi += pb[q * 2048 + (0 + e) * 128 + pi];
                    zf += pb[q * 2048 + (4 + e) * 128 + pi];
                    zg += pb[q * 2048 + (8 + e) * 128 + pi];
                    zo += pb[q * 2048 + (12 + e) * 128 + pi];
                }
                float h = lstm_cell(zi, zf, zg, zo, c2[e]);
                int u = uL2 + (e & 1), s = g + ((e & 2) ? 8 : 0);
                int idx = s * RS2 + u;
                __half hh = __float2half_rn(h);
                __half hl = __float2half_rn(h - __half2float(hh));
                h2hiW[idx] = hh;
                h2loW[idx] = hl;
                st16_rem_(rbase + A_H2HI + pw * 2304 + idx * 2, hh);
                st16_rem_(rbase + A_H2LO + pw * 2304 + idx * 2, hl);
                if (tt == T_SEQ - 1) g_h2last[(b0 + s) * 64 + u] = h;
            }
            arrive_rem_(rbase + A_MBH2);
        }
        __syncthreads();  // pbuf free before next L1 dump
    }
    CLUSTER_SYNC_();
}

// ---------------------------------------------------------------------------
// Phase B: Repeat(h2last) -> LSTM3 -> LSTM4 -> Dense(1). Cluster 2, N-split.
// ---------------------------------------------------------------------------
__global__ void __launch_bounds__(512, 1) __cluster_dims__(2, 1, 1)
phaseB_kernel(const float* __restrict__ W3, const float* __restrict__ b3,
              const float* __restrict__ b4, const float* __restrict__ Wd,
              const float* __restrict__ bd, float* __restrict__ out) {
    extern __shared__ char smem[];
    const int tid = threadIdx.x;
    const int w = tid >> 5, lane = tid & 31, g = lane >> 2, t = lane & 3;
    const int wl = w & 7, kh = w >> 3;    // L4
    const int wl2 = w & 3, kh2 = w >> 2;  // L3
    uint rk;
    asm("mov.u32 %0, %%cluster_ctarank;" : "=r"(rk));
    const uint peer = 1u - rk;
    const int b0 = (blockIdx.x >> 1) * BT;

    float* h2s = (float*)(smem + B_H2S);
    float* pb  = (float*)(smem + B_PBUF);
    float* pd  = (float*)(smem + B_PD);
    float* pd2 = (float*)(smem + B_PD2);
    const uint sbase = sm32_(smem);
    uint rbase;
    asm("mapa.shared::cluster.u32 %0, %1, %2;" : "=r"(rbase) : "r"(sbase), "r"(peer));

    for (int i = tid; i < BT * 64; i += 512) {
        int b = i >> 6, k = i & 63;
        h2s[b * 66 + k] = g_h2last[(b0 + b) * 64 + k];
    }
    for (int i = tid; i < 6656; i += 512) ((uint*)smem)[i] = 0u;  // h buffers
    if (tid == 0) {
        mbar_init_(sbase + B_MBH3, 128);
        mbar_init_(sbase + B_MBH4, 256);
        mbar_init_(sbase + B_MBD, 16);
    }
    __syncthreads();

    const int uL4 = 64 * (int)rk + 8 * wl + 2 * t;
    const int uL3 = 32 * (int)rk + 8 * wl2 + 2 * t;

    float b4v[8], wd0, wd1;
#pragma unroll
    for (int gg = 0; gg < 4; gg++)
#pragma unroll
        for (int e1 = 0; e1 < 2; e1++)
            b4v[gg * 2 + e1] = b4[gg * 128 + uL4 + e1];
    wd0 = Wd[uL4];
    wd1 = Wd[uL4 + 1];
    const float bdv = bd[0];

    // zx3 = b3 + h2last@W3 (fp32 exact; only kh2==0 warps need it)
    float zx[4][4];
    if (kh2 == 0) {
#pragma unroll
        for (int gg = 0; gg < 4; gg++)
#pragma unroll
            for (int e = 0; e < 4; e++) zx[gg][e] = b3[gg * 64 + uL3 + (e & 1)];
        for (int k = 0; k < 64; k++) {
            float ha = h2s[g * 66 + k], hb = h2s[(g + 8) * 66 + k];
#pragma unroll
            for (int gg = 0; gg < 4; gg++) {
                float w0 = W3[k * 256 + gg * 64 + uL3];
                float w1 = W3[k * 256 + gg * 64 + uL3 + 1];
                zx[gg][0] = fmaf(ha, w0, zx[gg][0]);
                zx[gg][1] = fmaf(ha, w1, zx[gg][1]);
                zx[gg][2] = fmaf(hb, w0, zx[gg][2]);
                zx[gg][3] = fmaf(hb, w1, zx[gg][3]);
            }
        }
    }
    CLUSTER_SYNC_();

    float c3[4], c4[4];
#pragma unroll
    for (int j = 0; j < 4; j++) { c3[j] = 0.0f; c4[j] = 0.0f; }

    for (int tt = 0; tt < T_SEQ; tt++) {
        const int pw = tt & 1, po = pw ^ 1;
        __half* h3hiR = (__half*)(smem + B_H3HI + po * 2304);
        __half* h3loR = (__half*)(smem + B_H3LO + po * 2304);
        __half* h3hiW = (__half*)(smem + B_H3HI + pw * 2304);
        __half* h3loW = (__half*)(smem + B_H3LO + pw * 2304);
        __half* h4hiR = (__half*)(smem + B_H4HI + po * 4352);
        __half* h4loR = (__half*)(smem + B_H4LO + po * 4352);
        __half* h4hiW = (__half*)(smem + B_H4HI + pw * 4352);
        __half* h4loW = (__half*)(smem + B_H4LO + pw * 4352);

        if (tt > 0) {
            waitp_(sbase + B_MBH3, (tt - 1) & 1);
            waitp_(sbase + B_MBH4, (tt - 1) & 1);
        }

        // ---- L3: z3 = zx3 + h3(t-1)@U3 (K=64 split 16x4) ----
        float C3[4][4];
        if (kh2 == 0) {
#pragma unroll
            for (int gg = 0; gg < 4; gg++)
#pragma unroll
                for (int e = 0; e < 4; e++) C3[gg][e] = zx[gg][e];
            gemm_part<1, 4>(C3, g_wfrag + SEC_L3, 0, 4 * rk + wl2, 8,
                            h3hiR, h3loR, RS2, g, t);
        } else {
#pragma unroll
            for (int gg = 0; gg < 4; gg++)
#pragma unroll
                for (int e = 0; e < 4; e++) C3[gg][e] = 0.0f;
            gemm_part<1, 4>(C3, g_wfrag + SEC_L3, kh2, 4 * rk + wl2, 8,
                            h3hiR + 16 * kh2, h3loR + 16 * kh2, RS2, g, t);
#pragma unroll
            for (int gg = 0; gg < 4; gg++)
#pragma unroll
                for (int e = 0; e < 4; e++)
                    pb[(kh2 - 1) * 2048 + (gg * 4 + e) * 128 + wl2 * 32 + lane] = C3[gg][e];
        }
        __syncthreads();
        if (kh2 == 0) {
#pragma unroll
            for (int e = 0; e < 4; e++) {
                int pi = wl2 * 32 + lane;
                float zi = C3[0][e], zf = C3[1][e], zg = C3[2][e], zo = C3[3][e];
#pragma unroll
                for (int q = 0; q < 3; q++) {
                    zi += pb[q * 2048 + (0 + e) * 128 + pi];
                    zf += pb[q * 2048 + (4 + e) * 128 + pi];
                    zg += pb[q * 2048 + (8 + e) * 128 + pi];
                    zo += pb[q * 2048 + (12 + e) * 128 + pi];
                }
                float h = lstm_cell(zi, zf, zg, zo, c3[e]);
                int u = uL3 + (e & 1), s = g + ((e & 2) ? 8 : 0);
                int idx = s * RS2 + u;
                __half hh = __float2half_rn(h);
                __half hl = __float2half_rn(h - __half2float(hh));
                h3hiW[idx] = hh;
                h3loW[idx] = hl;
                st16_rem_(rbase + B_H3HI + pw * 2304 + idx * 2, hh);
                st16_rem_(rbase + B_H3LO + pw * 2304 + idx * 2, hl);
            }
            arrive_rem_(rbase + B_MBH3);
        }
        __syncthreads();
        waitp_(sbase + B_MBH3, tt & 1);  // peer h3(t)

        // ---- L4: z4 = h3(t)@W4 + h4(t-1)@U4 + b4 (K=192 split 96/96) ----
        float C4[4][4];
        if (kh == 0) {
#pragma unroll
            for (int gg = 0; gg < 4; gg++)
#pragma unroll
                for (int e = 0; e < 4; e++) C4[gg][e] = b4v[gg * 2 + (e & 1)];
            gemm_part<4, 12>(C4, g_wfrag + SEC_L4, 0, 8 * rk + wl, 16,
                             h3hiW, h3loW, RS2, g, t);
            gemm_part<2, 12>(C4, g_wfrag + SEC_L4, 4, 8 * rk + wl, 16,
                             h4hiR, h4loR, RS1, g, t);
        } else {
#pragma unroll
            for (int gg = 0; gg < 4; gg++)
#pragma unroll
                for (int e = 0; e < 4; e++) C4[gg][e] = 0.0f;
            gemm_part<6, 12>(C4, g_wfrag + SEC_L4, 6, 8 * rk + wl, 16,
                             h4hiR + 32, h4loR + 32, RS1, g, t);
#pragma unroll
            for (int gg = 0; gg < 4; gg++)
#pragma unroll
                for (int e = 0; e < 4; e++)
                    pb[(gg * 4 + e) * 256 + wl * 32 + lane] = C4[gg][e];
        }
        __syncthreads();
        if (kh == 0) {
            float pA = 0.0f, pB = 0.0f;
#pragma unroll
            for (int e = 0; e < 4; e++) {
                int pi = wl * 32 + lane;
                float zi = C4[0][e] + pb[(0 + e) * 256 + pi];
                float zf = C4[1][e] + pb[(4 + e) * 256 + pi];
                float zg = C4[2][e] + pb[(8 + e) * 256 + pi];
                float zo = C4[3][e] + pb[(12 + e) * 256 + pi];
                float h = lstm_cell(zi, zf, zg, zo, c4[e]);
                int u = uL4 + (e & 1), s = g + ((e & 2) ? 8 : 0);
                int idx = s * RS1 + u;
                __half hh = __float2half_rn(h);
                __half hl = __float2half_rn(h - __half2float(hh));
                h4hiW[idx] = hh;
                h4loW[idx] = hl;
                st16_rem_(rbase + B_H4HI + pw * 4352 + idx * 2, hh);
                st16_rem_(rbase + B_H4LO + pw * 4352 + idx * 2, hl);
                float wv = (e & 1) ? wd1 : wd0;
                if (e & 2) pB = fmaf(h, wv, pB);
                else       pA = fmaf(h, wv, pA);
            }
            arrive_rem_(rbase + B_MBH4);
            pA += __shfl_xor_sync(0xffffffffu, pA, 1);
            pA += __shfl_xor_sync(0xffffffffu, pA, 2);
            pB += __shfl_xor_sync(0xffffffffu, pB, 1);
            pB += __shfl_xor_sync(0xffffffffu, pB, 2);
            if (t == 0) {
                pd[wl * 16 + g] = pA;
                pd[wl * 16 + 8 + g] = pB;
            }
        }
        __syncthreads();
        if (tid < 16) {
            float pr_ = 0.0f;
#pragma unroll
            for (int q = 0; q < 8; q++) pr_ += pd[q * 16 + tid];
            if (rk == 1) {
                st32_rem_(rbase + B_PD2 + tid * 4, pr_);
                arrive_rem_(rbase + B_MBD);
            } else {
                waitp_(sbase + B_MBD, tt & 1);
                out[(b0 + tid) * T_SEQ + tt] = pr_ + pd2[tid] + bdv;
            }
        }
    }
    CLUSTER_SYNC_();
}

// ---------------------------------------------------------------------------
extern "C" void kernel_launch(void* const* d_in, const int* in_sizes, int n_in,
                              void* d_out, int out_size) {
    const float* x  = (const float*)d_in[0];
    const float* W1 = (const float*)d_in[1];
    const float* U1 = (const float*)d_in[2];
    const float* b1 = (const float*)d_in[3];
    const float* W2 = (const float*)d_in[4];
    const float* U2 = (const float*)d_in[5];
    const float* b2 = (const float*)d_in[6];
    const float* W3 = (const float*)d_in[7];
    const float* U3 = (const float*)d_in[8];
    const float* b3 = (const float*)d_in[9];
    const float* W4 = (const float*)d_in[10];
    const float* U4 = (const float*)d_in[11];
    const float* b4 = (const float*)d_in[12];
    const float* Wd = (const float*)d_in[13];
    const float* bd = (const float*)d_in[14];
    float* out = (float*)d_out;

    cudaFuncSetAttribute(phaseA_kernel,
                         cudaFuncAttributeMaxDynamicSharedMemorySize, SMEMA_BYTES);
    cudaFuncSetAttribute(phaseB_kernel,
                         cudaFuncAttributeMaxDynamicSharedMemorySize, SMEMB_BYTES);

    pack_kernel<<<224, 256>>>(U1, W2, U2, U3, W4, U4);
    phaseA_kernel<<<NCTAS, 512, SMEMA_BYTES>>>(x, W1, b1, b2);
    phaseB_kernel<<<NCTAS, 512, SMEMB_BYTES>>>(W3, b3, b4, Wd, bd, out);
}

// round 16
// speedup vs baseline: 1.1374x; 1.1374x over previous
#include <cuda_runtime.h>
#include <cuda_fp16.h>

// MyModel_83597243450144 : 4-layer LSTM autoencoder, tensor-core split-fp16.
// B=2048, T=128, H1=128, H2=64. Gates i,f,g,o; g relu, h = o*relu(c).
// z = hi@Whi + hi@Wlo + lo@Whi via mma.sync.m16n8k16 (f16 in, f32 acc).
// R16: BT=32 (two 16-row mma blocks), 64 CTAs -> chip L2 weight traffic
// halves; each weight LDG.128 feeds 6 mmas. Same sync/layout as R14.

#define B_ALL 2048
#define T_SEQ 128
#define BT 32
#define NBLK (B_ALL / BT)  // 64 CTAs
#define RS1 136  // h row stride (halves) H=128 (128+8)
#define RS2 72   // H=64 (64+8)

typedef unsigned int uint;

// ---- device scratch ----
__device__ uint4 g_wfrag[57344];
__device__ float g_h2last[B_ALL * 64];

#define SEC_L1 0
#define SEC_L2 16384
#define SEC_L3 28672
#define SEC_L4 32768

// ---- dynamic smem layouts (bytes) ----
// Phase A
#define A_H1HI 0            // half[32*RS1] = 8704 B
#define A_H1LO 8704
#define A_H2HI 17408        // half[32*RS2] = 4608 B
#define A_H2LO 22016
#define A_XS   26624        // float[32][132] = 16896 B
#define A_PBUF 43520        // float[32][256] = 32768 B
#define SMEMA_BYTES 76288
// Phase B
#define B_H3HI 0            // 4608
#define B_H3LO 4608
#define B_H4HI 9216         // 8704
#define B_H4LO 17920
#define B_H2S  26624        // float[32][66] = 8448
#define B_PBUF 35072        // 32768
#define B_PD   67840        // float[16][32] = 2048
#define SMEMB_BYTES 69888

__device__ __forceinline__ float sigmoidf_(float v) {
    float r, h = 0.5f * v;
    asm("tanh.approx.f32 %0, %1;" : "=f"(r) : "f"(h));
    return fmaf(0.5f, r, 0.5f);
}
__device__ __forceinline__ uint packh_(__half lo, __half hi) {
    return (uint)__half_as_ushort(lo) | ((uint)__half_as_ushort(hi) << 16);
}
__device__ __forceinline__ uint ldh2_(const __half* p) { return *(const uint*)p; }
__device__ __forceinline__ void mma16816(float* c, uint a0, uint a1, uint a2,
                                         uint a3, uint b0, uint b1) {
    asm("mma.sync.aligned.m16n8k16.row.col.f32.f16.f16.f32 "
        "{%0,%1,%2,%3}, {%4,%5,%6,%7}, {%8,%9}, {%0,%1,%2,%3};"
        : "+f"(c[0]), "+f"(c[1]), "+f"(c[2]), "+f"(c[3])
        : "r"(a0), "r"(a1), "r"(a2), "r"(a3), "r"(b0), "r"(b1));
}
__device__ __forceinline__ float lstm_cell(float zi, float zf, float zg,
                                           float zo, float& c) {
    float iv = sigmoidf_(zi), fv = sigmoidf_(zf);
    float gv = fmaxf(zg, 0.0f), ov = sigmoidf_(zo);
    c = fmaf(fv, c, iv * gv);
    return ov * fmaxf(c, 0.0f);
}
__device__ __forceinline__ void split_store(__half* bhi, __half* blo, int idx,
                                            float h) {
    __half hh = __float2half_rn(h);
    bhi[idx] = hh;
    blo[idx] = __float2half_rn(h - __half2float(hh));
}

// GEMM partial, M=32 (2 row blocks). C[gg][8]: e = r*4 + e4 where r = row
// block, e4 = standard mma c index. nb = gg*nb_gs + nb_w.
template <int NKB, int KBTOT>
__device__ __forceinline__ void gemm_part(float (*C)[8], const uint4* wsec,
                                          int kb0, int nb_w, int nb_gs,
                                          const __half* bhi, const __half* blo,
                                          int rs, int g, int t) {
    const uint4* wl_ = wsec + (threadIdx.x & 31);
#pragma unroll
    for (int kk = 0; kk < NKB; kk++) {
        const int kb = kb0 + kk;
        const int c0 = kk * 16 + 2 * t;
        // row block 0 (samples 0-15): rows g, g+8
        uint a0 = ldh2_(bhi + g * rs + c0);
        uint a1 = ldh2_(bhi + (g + 8) * rs + c0);
        uint a2 = ldh2_(bhi + g * rs + c0 + 8);
        uint a3 = ldh2_(bhi + (g + 8) * rs + c0 + 8);
        uint l0 = ldh2_(blo + g * rs + c0);
        uint l1 = ldh2_(blo + (g + 8) * rs + c0);
        uint l2 = ldh2_(blo + g * rs + c0 + 8);
        uint l3 = ldh2_(blo + (g + 8) * rs + c0 + 8);
        // row block 1 (samples 16-31): rows 16+g, 24+g
        uint b0_ = ldh2_(bhi + (16 + g) * rs + c0);
        uint b1_ = ldh2_(bhi + (24 + g) * rs + c0);
        uint b2_ = ldh2_(bhi + (16 + g) * rs + c0 + 8);
        uint b3_ = ldh2_(bhi + (24 + g) * rs + c0 + 8);
        uint m0 = ldh2_(blo + (16 + g) * rs + c0);
        uint m1 = ldh2_(blo + (24 + g) * rs + c0);
        uint m2 = ldh2_(blo + (16 + g) * rs + c0 + 8);
        uint m3 = ldh2_(blo + (24 + g) * rs + c0 + 8);
#pragma unroll
        for (int gg = 0; gg < 4; gg++) {
            int nb = gg * nb_gs + nb_w;
            uint4 wf = wl_[(nb * KBTOT + kb) * 32];
            float* c = C[gg];
            mma16816(c, a0, a1, a2, a3, wf.x, wf.y);
            mma16816(c, a0, a1, a2, a3, wf.z, wf.w);
            mma16816(c, l0, l1, l2, l3, wf.x, wf.y);
            mma16816(c + 4, b0_, b1_, b2_, b3_, wf.x, wf.y);
            mma16816(c + 4, b0_, b1_, b2_, b3_, wf.z, wf.w);
            mma16816(c + 4, m0, m1, m2, m3, wf.x, wf.y);
        }
    }
}

// ---------------------------------------------------------------------------
__global__ void pack_kernel(const float* __restrict__ U1,
                            const float* __restrict__ W2, const float* __restrict__ U2,
                            const float* __restrict__ U3,
                            const float* __restrict__ W4, const float* __restrict__ U4) {
    int e = blockIdx.x * 256 + threadIdx.x;
    if (e >= 57344) return;
    int sec, KB, idx;
    if (e < 16384)      { sec = 0; KB = 8;  idx = e; }
    else if (e < 28672) { sec = 1; KB = 12; idx = e - 16384; }
    else if (e < 32768) { sec = 2; KB = 4;  idx = e - 28672; }
    else                { sec = 3; KB = 12; idx = e - 32768; }
    int lane = idx & 31, rest = idx >> 5;
    int kb = rest % KB, nb = rest / KB;
    int g = lane >> 2, t = lane & 3;
    int n = nb * 8 + g;
    __half h[4], l[4];
#pragma unroll
    for (int r = 0; r < 4; r++) {
        int k = kb * 16 + 2 * t + (r & 1) + (r >> 1) * 8;
        float v;
        if (sec == 0)      v = U1[k * 512 + n];
        else if (sec == 1) v = (k < 128) ? W2[k * 256 + n] : U2[(k - 128) * 256 + n];
        else if (sec == 2) v = U3[k * 256 + n];
        else               v = (k < 64) ? W4[k * 512 + n] : U4[(k - 64) * 512 + n];
        h[r] = __float2half_rn(v);
        l[r] = __float2half_rn(v - __half2float(h[r]));
    }
    uint4 o;
    o.x = packh_(h[0], h[1]);
    o.y = packh_(h[2], h[3]);
    o.z = packh_(l[0], l[1]);
    o.w = packh_(l[2], l[3]);
    g_wfrag[e] = o;
}

// ---------------------------------------------------------------------------
// Phase A: LSTM1 (H=128) + LSTM2 (H=64). 512 threads, 32 samples/CTA.
// L1: full K per warp, nb = gg*16 + w. L2: K split 96/96 by w>>3; partials
// via pbuf; epilogue on warps 0-7.
// ---------------------------------------------------------------------------
__global__ void __launch_bounds__(512, 1)
phaseA_kernel(const float* __restrict__ x, const float* __restrict__ W1,
              const float* __restrict__ b1, const float* __restrict__ b2) {
    extern __shared__ char smem[];
    __half* h1hi = (__half*)(smem + A_H1HI);
    __half* h1lo = (__half*)(smem + A_H1LO);
    __half* h2hi = (__half*)(smem + A_H2HI);
    __half* h2lo = (__half*)(smem + A_H2LO);
    float*  xs   = (float*)(smem + A_XS);
    float*  pb   = (float*)(smem + A_PBUF);

    const int tid = threadIdx.x;
    const int w = tid >> 5, lane = tid & 31, g = lane >> 2, t = lane & 3;
    const int wl = w & 7, kh = w >> 3;
    const int b0 = blockIdx.x * BT;

    for (int i = tid; i < BT * T_SEQ; i += 512) {
        int b = i >> 7, s = i & 127;
        xs[b * 132 + s] = x[(b0 + b) * T_SEQ + s];
    }
    for (int i = tid; i < 6656; i += 512) ((uint*)smem)[i] = 0u;  // h buffers

    const int u1 = 8 * w + 2 * t;    // layer-1 unit base (16 warps)
    const int u2 = 8 * wl + 2 * t;   // layer-2 unit base (warp halves)

    float b1v[8], w1v[8], b2v[8];
#pragma unroll
    for (int gg = 0; gg < 4; gg++)
#pragma unroll
        for (int e1 = 0; e1 < 2; e1++) {
            int col = gg * 128 + u1 + e1;
            b1v[gg * 2 + e1] = b1[col];
            w1v[gg * 2 + e1] = W1[col];
            b2v[gg * 2 + e1] = b2[gg * 64 + u2 + e1];
        }

    float c1[8], c2[8];
#pragma unroll
    for (int j = 0; j < 8; j++) { c1[j] = 0.0f; c2[j] = 0.0f; }

    __syncthreads();

    for (int tt = 0; tt < T_SEQ; tt++) {
        // ---- layer 1: z1 = x*W1 + h1@U1 + b1 (full K per warp) ----
        float C1[4][8];
        {
            float xv[4];
            xv[0] = xs[g * 132 + tt];
            xv[1] = xs[(g + 8) * 132 + tt];
            xv[2] = xs[(16 + g) * 132 + tt];
            xv[3] = xs[(24 + g) * 132 + tt];
#pragma unroll
            for (int gg = 0; gg < 4; gg++)
#pragma unroll
                for (int e = 0; e < 8; e++) {
                    int e4 = e & 3, r = e >> 2;
                    int idx = gg * 2 + (e4 & 1);
                    float xvv = xv[r * 2 + ((e4 & 2) ? 1 : 0)];
                    C1[gg][e] = fmaf(xvv, w1v[idx], b1v[idx]);
                }
        }
        gemm_part<8, 8>(C1, g_wfrag + SEC_L1, 0, w, 16, h1hi, h1lo, RS1, g, t);
        __syncthreads();  // all h1(t-1) reads done
#pragma unroll
        for (int e = 0; e < 8; e++) {
            int e4 = e & 3, r = e >> 2;
            int u = u1 + (e4 & 1);
            int s = r * 16 + g + ((e4 & 2) ? 8 : 0);
            float h = lstm_cell(C1[0][e], C1[1][e], C1[2][e], C1[3][e], c1[e]);
            split_store(h1hi, h1lo, s * RS1 + u, h);
        }
        __syncthreads();  // h1(t) visible

        // ---- layer 2: z2 = h1@W2 + h2@U2 + b2 (K=192 split 96/96) ----
        float C2[4][8];
        if (kh == 0) {
#pragma unroll
            for (int gg = 0; gg < 4; gg++)
#pragma unroll
                for (int e = 0; e < 8; e++) C2[gg][e] = b2v[gg * 2 + (e & 1)];
            gemm_part<6, 12>(C2, g_wfrag + SEC_L2, 0, wl, 8, h1hi, h1lo, RS1, g, t);
        } else {
#pragma unroll
            for (int gg = 0; gg < 4; gg++)
#pragma unroll
                for (int e = 0; e < 8; e++) C2[gg][e] = 0.0f;
            gemm_part<2, 12>(C2, g_wfrag + SEC_L2, 6, wl, 8, h1hi + 96, h1lo + 96, RS1, g, t);
            gemm_part<4, 12>(C2, g_wfrag + SEC_L2, 8, wl, 8, h2hi, h2lo, RS2, g, t);
#pragma unroll
            for (int gg = 0; gg < 4; gg++)
#pragma unroll
                for (int e = 0; e < 8; e++)
                    pb[(gg * 8 + e) * 256 + wl * 32 + lane] = C2[gg][e];
        }
        __syncthreads();  // partials visible; all h1(t)/h2(t-1) reads done
        if (kh == 0) {
#pragma unroll
            for (int e = 0; e < 8; e++) {
                int e4 = e & 3, r = e >> 2;
                int u = u2 + (e4 & 1);
                int s = r * 16 + g + ((e4 & 2) ? 8 : 0);
                int pi = wl * 32 + lane;
                float zi = C2[0][e] + pb[(0 * 8 + e) * 256 + pi];
                float zf = C2[1][e] + pb[(1 * 8 + e) * 256 + pi];
                float zg = C2[2][e] + pb[(2 * 8 + e) * 256 + pi];
                float zo = C2[3][e] + pb[(3 * 8 + e) * 256 + pi];
                float h = lstm_cell(zi, zf, zg, zo, c2[e]);
                split_store(h2hi, h2lo, s * RS2 + u, h);
                if (tt == T_SEQ - 1) g_h2last[(b0 + s) * 64 + u] = h;
            }
        }
        // h2(t) writes vs next-step reads: separated by next step's 2 bars
    }
}

// ---------------------------------------------------------------------------
// Phase B: Repeat(h2last) -> LSTM3 (64) -> LSTM4 (128) -> Dense(1).
// L3: K=64 split 32/32; L4: full K per warp. Dense via shfl + pd[16][32].
// ---------------------------------------------------------------------------
__global__ void __launch_bounds__(512, 1)
phaseB_kernel(const float* __restrict__ W3, const float* __restrict__ b3,
              const float* __restrict__ b4, const float* __restrict__ Wd,
              const float* __restrict__ bd, float* __restrict__ out) {
    extern __shared__ char smem[];
    __half* h3hi = (__half*)(smem + B_H3HI);
    __half* h3lo = (__half*)(smem + B_H3LO);
    __half* h4hi = (__half*)(smem + B_H4HI);
    __half* h4lo = (__half*)(smem + B_H4LO);
    float*  h2s  = (float*)(smem + B_H2S);
    float*  pb   = (float*)(smem + B_PBUF);
    float*  pd   = (float*)(smem + B_PD);

    const int tid = threadIdx.x;
    const int w = tid >> 5, lane = tid & 31, g = lane >> 2, t = lane & 3;
    const int wl = w & 7, kh = w >> 3;
    const int b0 = blockIdx.x * BT;

    for (int i = tid; i < BT * 64; i += 512) {
        int b = i >> 6, k = i & 63;
        h2s[b * 66 + k] = g_h2last[(b0 + b) * 64 + k];
    }
    for (int i = tid; i < 6656; i += 512) ((uint*)smem)[i] = 0u;  // h buffers

    const int u1 = 8 * w + 2 * t;   // layer-4 unit base
    const int u2 = 8 * wl + 2 * t;  // layer-3 unit base

    float b4v[8], wd0, wd1;
#pragma unroll
    for (int gg = 0; gg < 4; gg++)
#pragma unroll
        for (int e1 = 0; e1 < 2; e1++)
            b4v[gg * 2 + e1] = b4[gg * 128 + u1 + e1];
    wd0 = Wd[u1]; wd1 = Wd[u1 + 1];
    const float bdv = bd[0];

    __syncthreads();

    // zx3 = b3 + h2last @ W3 (fp32 exact, constant over t) — warps 0-7 use it
    float zx[4][8];
#pragma unroll
    for (int gg = 0; gg < 4; gg++)
#pragma unroll
        for (int e = 0; e < 8; e++) zx[gg][e] = b3[gg * 64 + u2 + (e & 1)];
    for (int k = 0; k < 64; k++) {
        float ha = h2s[g * 66 + k];
        float hb = h2s[(g + 8) * 66 + k];
        float hc = h2s[(16 + g) * 66 + k];
        float hd = h2s[(24 + g) * 66 + k];
#pragma unroll
        for (int gg = 0; gg < 4; gg++) {
            float w0 = W3[k * 256 + gg * 64 + u2];
            float w1 = W3[k * 256 + gg * 64 + u2 + 1];
            zx[gg][0] = fmaf(ha, w0, zx[gg][0]);
            zx[gg][1] = fmaf(ha, w1, zx[gg][1]);
            zx[gg][2] = fmaf(hb, w0, zx[gg][2]);
            zx[gg][3] = fmaf(hb, w1, zx[gg][3]);
            zx[gg][4] = fmaf(hc, w0, zx[gg][4]);
            zx[gg][5] = fmaf(hc, w1, zx[gg][5]);
            zx[gg][6] = fmaf(hd, w0, zx[gg][6]);
            zx[gg][7] = fmaf(hd, w1, zx[gg][7]);
        }
    }

    float c3[8], c4[8];
#pragma unroll
    for (int j = 0; j < 8; j++) { c3[j] = 0.0f; c4[j] = 0.0f; }

    for (int tt = 0; tt < T_SEQ; tt++) {
        // ---- layer 3: z3 = zx3 + h3@U3 (K=64 split 32/32) ----
        float C3[4][8];
        if (kh == 0) {
#pragma unroll
            for (int gg = 0; gg < 4; gg++)
#pragma unroll
                for (int e = 0; e < 8; e++) C3[gg][e] = zx[gg][e];
            gemm_part<2, 4>(C3, g_wfrag + SEC_L3, 0, wl, 8, h3hi, h3lo, RS2, g, t);
        } else {
#pragma unroll
            for (int gg = 0; gg < 4; gg++)
#pragma unroll
                for (int e = 0; e < 8; e++) C3[gg][e] = 0.0f;
            gemm_part<2, 4>(C3, g_wfrag + SEC_L3, 2, wl, 8, h3hi + 32, h3lo + 32, RS2, g, t);
#pragma unroll
            for (int gg = 0; gg < 4; gg++)
#pragma unroll
                for (int e = 0; e < 8; e++)
                    pb[(gg * 8 + e) * 256 + wl * 32 + lane] = C3[gg][e];
        }
        __syncthreads();  // partials visible; h3(t-1) reads done
        if (kh == 0) {
#pragma unroll
            for (int e = 0; e < 8; e++) {
                int e4 = e & 3, r = e >> 2;
                int u = u2 + (e4 & 1);
                int s = r * 16 + g + ((e4 & 2) ? 8 : 0);
                int pi = wl * 32 + lane;
                float zi = C3[0][e] + pb[(0 * 8 + e) * 256 + pi];
                float zf = C3[1][e] + pb[(1 * 8 + e) * 256 + pi];
                float zg = C3[2][e] + pb[(2 * 8 + e) * 256 + pi];
                float zo = C3[3][e] + pb[(3 * 8 + e) * 256 + pi];
                float h = lstm_cell(zi, zf, zg, zo, c3[e]);
                split_store(h3hi, h3lo, s * RS2 + u, h);
            }
        }
        __syncthreads();  // h3(t) visible

        // ---- layer 4: z4 = h3@W4 + h4@U4 + b4 (full K per warp) ----
        float C4[4][8];
#pragma unroll
        for (int gg = 0; gg < 4; gg++)
#pragma unroll
            for (int e = 0; e < 8; e++) C4[gg][e] = b4v[gg * 2 + (e & 1)];
        gemm_part<4, 12>(C4, g_wfrag + SEC_L4, 0, w, 16, h3hi, h3lo, RS2, g, t);
        gemm_part<8, 12>(C4, g_wfrag + SEC_L4, 4, w, 16, h4hi, h4lo, RS1, g, t);
        __syncthreads();  // h4(t-1) + h3(t) reads done
        {
            float p[4] = {0.0f, 0.0f, 0.0f, 0.0f};
#pragma unroll
            for (int e = 0; e < 8; e++) {
                int e4 = e & 3, r = e >> 2;
                int u = u1 + (e4 & 1);
                int s = r * 16 + g + ((e4 & 2) ? 8 : 0);
                float h = lstm_cell(C4[0][e], C4[1][e], C4[2][e], C4[3][e], c4[e]);
                split_store(h4hi, h4lo, s * RS1 + u, h);
                float wv = (e4 & 1) ? wd1 : wd0;
                p[r * 2 + ((e4 & 2) ? 1 : 0)] = fmaf(h, wv, p[r * 2 + ((e4 & 2) ? 1 : 0)]);
            }
#pragma unroll
            for (int q = 0; q < 4; q++) {
                p[q] += __shfl_xor_sync(0xffffffffu, p[q], 1);
                p[q] += __shfl_xor_sync(0xffffffffu, p[q], 2);
            }
            if (t == 0) {
                pd[w * 32 + g]      = p[0];
                pd[w * 32 + 8 + g]  = p[1];
                pd[w * 32 + 16 + g] = p[2];
                pd[w * 32 + 24 + g] = p[3];
            }
        }
        __syncthreads();  // h4(t) + pd visible
        if (tid < 32) {
            float s_ = bdv;
#pragma unroll
            for (int wi = 0; wi < 16; wi++) s_ += pd[wi * 32 + tid];
            out[(b0 + tid) * T_SEQ + tt] = s_;
        }
        // pd rewritten only after next step's barriers -> safe
    }
}

// ---------------------------------------------------------------------------
extern "C" void kernel_launch(void* const* d_in, const int* in_sizes, int n_in,
                              void* d_out, int out_size) {
    const float* x  = (const float*)d_in[0];
    const float* W1 = (const float*)d_in[1];
    const float* U1 = (const float*)d_in[2];
    const float* b1 = (const float*)d_in[3];
    const float* W2 = (const float*)d_in[4];
    const float* U2 = (const float*)d_in[5];
    const float* b2 = (const float*)d_in[6];
    const float* W3 = (const float*)d_in[7];
    const float* U3 = (const float*)d_in[8];
    const float* b3 = (const float*)d_in[9];
    const float* W4 = (const float*)d_in[10];
    const float* U4 = (const float*)d_in[11];
    const float* b4 = (const float*)d_in[12];
    const float* Wd = (const float*)d_in[13];
    const float* bd = (const float*)d_in[14];
    float* out = (float*)d_out;

    cudaFuncSetAttribute(phaseA_kernel,
                         cudaFuncAttributeMaxDynamicSharedMemorySize, SMEMA_BYTES);
    cudaFuncSetAttribute(phaseB_kernel,
                         cudaFuncAttributeMaxDynamicSharedMemorySize, SMEMB_BYTES);

    pack_kernel<<<224, 256>>>(U1, W2, U2, U3, W4, U4);
    phaseA_kernel<<<NBLK, 512, SMEMA_BYTES>>>(x, W1, b1, b2);
    phaseB_kernel<<<NBLK, 512, SMEMB_BYTES>>>(W3, b3, b4, Wd, bd, out);
}

// round 17
// speedup vs baseline: 1.2488x; 1.0980x over previous
#include <cuda_runtime.h>
#include <cuda_fp16.h>

// MyModel_83597243450144 : 4-layer LSTM autoencoder, tensor-core split-fp16.
// B=2048, T=128, H1=128, H2=64. Gates i,f,g,o; g relu, h = o*relu(c).
// z = hi@Whi + hi@Wlo + lo@Whi via mma.sync.m16n8k16 (f16 in, f32 acc).
//
// R17 = R15 cluster N-split + R16 M=32 gemm, with the grid fixed:
// 64 clusters x 2 CTAs = 128 CTAs (one wave). Each cluster owns 32 samples;
// each CTA computes HALF the units of every layer -> chip L2 weight traffic
// halves vs R14 while per-CTA mma work stays at R14 level. h halves are
// exchanged via DSMEM stores + mbarrier handshake (parity double-buffered).

#define B_ALL 2048
#define T_SEQ 128
#define BT 32
#define NCTAS 128            // 64 clusters of 2
#define RS1 136              // h row stride (halves) H=128 (128+8)
#define RS2 72               // H=64 (64+8)

typedef unsigned int uint;

// ---- device scratch ----
__device__ uint4 g_wfrag[57344];
__device__ float g_h2last[B_ALL * 64];

#define SEC_L1 0
#define SEC_L2 16384
#define SEC_L3 28672
#define SEC_L4 32768

// ---- dynamic smem layouts (bytes) ----
// Phase A
#define A_H1HI 0        // [2][32*RS1] halves, parity stride 8704 B
#define A_H1LO 17408
#define A_H2HI 34816    // [2][32*RS2], parity stride 4608 B
#define A_H2LO 44032
#define A_XS   53248    // float[32][132] = 16896
#define A_PBUF 70144    // float[12288] = 49152
#define A_MBH1 119296
#define A_MBH2 119304
#define SMEMA_BYTES 119328
// Phase B
#define B_H3HI 0        // parity stride 4608
#define B_H3LO 9216
#define B_H4HI 18432    // parity stride 8704
#define B_H4LO 35840
#define B_H2S  53248    // float[32][66] = 8448
#define B_PBUF 61696    // 49152
#define B_PD   110848   // float[8][32] = 1024
#define B_PD2  111872   // float[32] = 128
#define B_MBH3 112000
#define B_MBH4 112008
#define B_MBD  112016
#define SMEMB_BYTES 112032

__device__ __forceinline__ float sigmoidf_(float v) {
    float r, h = 0.5f * v;
    asm("tanh.approx.f32 %0, %1;" : "=f"(r) : "f"(h));
    return fmaf(0.5f, r, 0.5f);
}
__device__ __forceinline__ uint packh_(__half lo, __half hi) {
    return (uint)__half_as_ushort(lo) | ((uint)__half_as_ushort(hi) << 16);
}
__device__ __forceinline__ uint ldh2_(const __half* p) { return *(const uint*)p; }
__device__ __forceinline__ void mma16816(float* c, uint a0, uint a1, uint a2,
                                         uint a3, uint b0, uint b1) {
    asm("mma.sync.aligned.m16n8k16.row.col.f32.f16.f16.f32 "
        "{%0,%1,%2,%3}, {%4,%5,%6,%7}, {%8,%9}, {%0,%1,%2,%3};"
        : "+f"(c[0]), "+f"(c[1]), "+f"(c[2]), "+f"(c[3])
        : "r"(a0), "r"(a1), "r"(a2), "r"(a3), "r"(b0), "r"(b1));
}
__device__ __forceinline__ float lstm_cell(float zi, float zf, float zg,
                                           float zo, float& c) {
    float iv = sigmoidf_(zi), fv = sigmoidf_(zf);
    float gv = fmaxf(zg, 0.0f), ov = sigmoidf_(zo);
    c = fmaf(fv, c, iv * gv);
    return ov * fmaxf(c, 0.0f);
}
__device__ __forceinline__ uint sm32_(const void* p) {
    uint r;
    asm("{.reg .u64 t; cvta.to.shared.u64 t, %1; cvt.u32.u64 %0, t;}"
        : "=r"(r) : "l"(p));
    return r;
}
__device__ __forceinline__ void mbar_init_(uint a, uint n) {
    asm volatile("mbarrier.init.shared.b64 [%0], %1;" :: "r"(a), "r"(n) : "memory");
}
__device__ __forceinline__ void arrive_rem_(uint remote_addr) {
    asm volatile("mbarrier.arrive.release.cluster.shared::cluster.b64 _, [%0];"
                 :: "r"(remote_addr) : "memory");
}
__device__ __forceinline__ void waitp_(uint mbar, uint par) {
    uint done = 0;
    while (!done) {
        asm volatile(
            "{\n\t.reg .pred p;\n\t"
            "mbarrier.try_wait.parity.acquire.cluster.shared::cta.b64 p, [%1], %2, 0x989680;\n\t"
            "selp.b32 %0, 1, 0, p;\n\t}"
            : "=r"(done) : "r"(mbar), "r"(par) : "memory");
    }
}
__device__ __forceinline__ void st16_rem_(uint addr, __half v) {
    asm volatile("st.shared::cluster.u16 [%0], %1;"
                 :: "r"(addr), "h"((unsigned short)__half_as_ushort(v)) : "memory");
}
__device__ __forceinline__ void st32_rem_(uint addr, float v) {
    asm volatile("st.shared::cluster.b32 [%0], %1;"
                 :: "r"(addr), "r"(__float_as_uint(v)) : "memory");
}
#define CLUSTER_SYNC_() do { \
    asm volatile("barrier.cluster.arrive.aligned;" ::: "memory"); \
    asm volatile("barrier.cluster.wait.aligned;" ::: "memory"); } while (0)

// GEMM partial, M=32 (2 row blocks). C[gg][8]: e = r*4 + e4, r = row block.
// Weights kb0..kb0+NKB-1 of a KBTOT-block section; A cols kk*16 from (bhi,blo).
template <int NKB, int KBTOT>
__device__ __forceinline__ void gemm_part(float (*C)[8], const uint4* wsec,
                                          int kb0, int nb_w, int nb_gs,
                                          const __half* bhi, const __half* blo,
                                          int rs, int g, int t) {
    const uint4* wl_ = wsec + (threadIdx.x & 31);
#pragma unroll
    for (int kk = 0; kk < NKB; kk++) {
        const int kb = kb0 + kk;
        const int c0 = kk * 16 + 2 * t;
        uint a0 = ldh2_(bhi + g * rs + c0);
        uint a1 = ldh2_(bhi + (g + 8) * rs + c0);
        uint a2 = ldh2_(bhi + g * rs + c0 + 8);
        uint a3 = ldh2_(bhi + (g + 8) * rs + c0 + 8);
        uint l0 = ldh2_(blo + g * rs + c0);
        uint l1 = ldh2_(blo + (g + 8) * rs + c0);
        uint l2 = ldh2_(blo + g * rs + c0 + 8);
        uint l3 = ldh2_(blo + (g + 8) * rs + c0 + 8);
        uint b0_ = ldh2_(bhi + (16 + g) * rs + c0);
        uint b1_ = ldh2_(bhi + (24 + g) * rs + c0);
        uint b2_ = ldh2_(bhi + (16 + g) * rs + c0 + 8);
        uint b3_ = ldh2_(bhi + (24 + g) * rs + c0 + 8);
        uint m0 = ldh2_(blo + (16 + g) * rs + c0);
        uint m1 = ldh2_(blo + (24 + g) * rs + c0);
        uint m2 = ldh2_(blo + (16 + g) * rs + c0 + 8);
        uint m3 = ldh2_(blo + (24 + g) * rs + c0 + 8);
#pragma unroll
        for (int gg = 0; gg < 4; gg++) {
            int nb = gg * nb_gs + nb_w;
            uint4 wf = wl_[(nb * KBTOT + kb) * 32];
            float* c = C[gg];
            mma16816(c, a0, a1, a2, a3, wf.x, wf.y);
            mma16816(c, a0, a1, a2, a3, wf.z, wf.w);
            mma16816(c, l0, l1, l2, l3, wf.x, wf.y);
            mma16816(c + 4, b0_, b1_, b2_, b3_, wf.x, wf.y);
            mma16816(c + 4, b0_, b1_, b2_, b3_, wf.z, wf.w);
            mma16816(c + 4, m0, m1, m2, m3, wf.x, wf.y);
        }
    }
}

// ---------------------------------------------------------------------------
__global__ void pack_kernel(const float* __restrict__ U1,
                            const float* __restrict__ W2, const float* __restrict__ U2,
                            const float* __restrict__ U3,
                            const float* __restrict__ W4, const float* __restrict__ U4) {
    int e = blockIdx.x * 256 + threadIdx.x;
    if (e >= 57344) return;
    int sec, KB, idx;
    if (e < 16384)      { sec = 0; KB = 8;  idx = e; }
    else if (e < 28672) { sec = 1; KB = 12; idx = e - 16384; }
    else if (e < 32768) { sec = 2; KB = 4;  idx = e - 28672; }
    else                { sec = 3; KB = 12; idx = e - 32768; }
    int lane = idx & 31, rest = idx >> 5;
    int kb = rest % KB, nb = rest / KB;
    int g = lane >> 2, t = lane & 3;
    int n = nb * 8 + g;
    __half h[4], l[4];
#pragma unroll
    for (int r = 0; r < 4; r++) {
        int k = kb * 16 + 2 * t + (r & 1) + (r >> 1) * 8;
        float v;
        if (sec == 0)      v = U1[k * 512 + n];
        else if (sec == 1) v = (k < 128) ? W2[k * 256 + n] : U2[(k - 128) * 256 + n];
        else if (sec == 2) v = U3[k * 256 + n];
        else               v = (k < 64) ? W4[k * 512 + n] : U4[(k - 64) * 512 + n];
        h[r] = __float2half_rn(v);
        l[r] = __float2half_rn(v - __half2float(h[r]));
    }
    uint4 o;
    o.x = packh_(h[0], h[1]);
    o.y = packh_(h[2], h[3]);
    o.z = packh_(l[0], l[1]);
    o.w = packh_(l[2], l[3]);
    g_wfrag[e] = o;
}

// ---------------------------------------------------------------------------
// Phase A: LSTM1 + LSTM2. Cluster 2, 32 samples/cluster, half units per CTA.
// ---------------------------------------------------------------------------
__global__ void __launch_bounds__(512, 1) __cluster_dims__(2, 1, 1)
phaseA_kernel(const float* __restrict__ x, const float* __restrict__ W1,
              const float* __restrict__ b1, const float* __restrict__ b2) {
    extern __shared__ char smem[];
    const int tid = threadIdx.x;
    const int w = tid >> 5, lane = tid & 31, g = lane >> 2, t = lane & 3;
    const int wl = w & 7, kh = w >> 3;    // L1: unit slice / K half
    const int wl2 = w & 3, kh2 = w >> 2;  // L2: unit slice / K quarter
    uint rk;
    asm("mov.u32 %0, %%cluster_ctarank;" : "=r"(rk));
    const uint peer = 1u - rk;
    const int b0 = (blockIdx.x >> 1) * BT;

    float* xs = (float*)(smem + A_XS);
    float* pb = (float*)(smem + A_PBUF);
    const uint sbase = sm32_(smem);
    uint rbase;
    asm("mapa.shared::cluster.u32 %0, %1, %2;" : "=r"(rbase) : "r"(sbase), "r"(peer));

    for (int i = tid; i < BT * T_SEQ; i += 512) {
        int b = i >> 7, s = i & 127;
        xs[b * 132 + s] = x[(b0 + b) * T_SEQ + s];
    }
    for (int i = tid; i < 13312; i += 512) ((uint*)smem)[i] = 0u;  // h buffers
    if (tid == 0) {
        mbar_init_(sbase + A_MBH1, 256);
        mbar_init_(sbase + A_MBH2, 128);
    }
    __syncthreads();
    CLUSTER_SYNC_();

    const int uL1 = 64 * (int)rk + 8 * wl + 2 * t;
    const int uL2 = 32 * (int)rk + 8 * wl2 + 2 * t;

    float b1v[8], w1v[8], b2v[8];
#pragma unroll
    for (int gg = 0; gg < 4; gg++)
#pragma unroll
        for (int e1 = 0; e1 < 2; e1++) {
            int col = gg * 128 + uL1 + e1;
            b1v[gg * 2 + e1] = b1[col];
            w1v[gg * 2 + e1] = W1[col];
            b2v[gg * 2 + e1] = b2[gg * 64 + uL2 + e1];
        }
    float c1[8], c2[8];
#pragma unroll
    for (int j = 0; j < 8; j++) { c1[j] = 0.0f; c2[j] = 0.0f; }

    for (int tt = 0; tt < T_SEQ; tt++) {
        const int pw = tt & 1, po = pw ^ 1;
        __half* h1hiR = (__half*)(smem + A_H1HI + po * 8704);
        __half* h1loR = (__half*)(smem + A_H1LO + po * 8704);
        __half* h1hiW = (__half*)(smem + A_H1HI + pw * 8704);
        __half* h1loW = (__half*)(smem + A_H1LO + pw * 8704);
        __half* h2hiR = (__half*)(smem + A_H2HI + po * 4608);
        __half* h2loR = (__half*)(smem + A_H2LO + po * 4608);
        __half* h2hiW = (__half*)(smem + A_H2HI + pw * 4608);
        __half* h2loW = (__half*)(smem + A_H2LO + pw * 4608);

        if (tt > 0) waitp_(sbase + A_MBH2, (tt - 1) & 1);  // peer h2(t-1)

        // ---- L1: z1 = x*W1 + h1(t-1)@U1 + b1 (K=128 split 64/64) ----
        float C1[4][8];
        if (kh == 0) {
            float xv[4];
            xv[0] = xs[g * 132 + tt];
            xv[1] = xs[(g + 8) * 132 + tt];
            xv[2] = xs[(16 + g) * 132 + tt];
            xv[3] = xs[(24 + g) * 132 + tt];
#pragma unroll
            for (int gg = 0; gg < 4; gg++)
#pragma unroll
                for (int e = 0; e < 8; e++) {
                    int e4 = e & 3, r = e >> 2;
                    int idx = gg * 2 + (e4 & 1);
                    float xvv = xv[r * 2 + ((e4 & 2) ? 1 : 0)];
                    C1[gg][e] = fmaf(xvv, w1v[idx], b1v[idx]);
                }
            gemm_part<4, 8>(C1, g_wfrag + SEC_L1, 0, 8 * rk + wl, 16,
                            h1hiR, h1loR, RS1, g, t);
        } else {
#pragma unroll
            for (int gg = 0; gg < 4; gg++)
#pragma unroll
                for (int e = 0; e < 8; e++) C1[gg][e] = 0.0f;
            gemm_part<4, 8>(C1, g_wfrag + SEC_L1, 4, 8 * rk + wl, 16,
                            h1hiR + 64, h1loR + 64, RS1, g, t);
#pragma unroll
            for (int gg = 0; gg < 4; gg++)
#pragma unroll
                for (int e = 0; e < 8; e++)
                    pb[(gg * 8 + e) * 256 + wl * 32 + lane] = C1[gg][e];
        }
        __syncthreads();
        if (kh == 0) {
#pragma unroll
            for (int e = 0; e < 8; e++) {
                int e4 = e & 3, r = e >> 2;
                int pi = wl * 32 + lane;
                float zi = C1[0][e] + pb[(0 * 8 + e) * 256 + pi];
                float zf = C1[1][e] + pb[(1 * 8 + e) * 256 + pi];
                float zg = C1[2][e] + pb[(2 * 8 + e) * 256 + pi];
                float zo = C1[3][e] + pb[(3 * 8 + e) * 256 + pi];
                float h = lstm_cell(zi, zf, zg, zo, c1[e]);
                int u = uL1 + (e4 & 1), s = r * 16 + g + ((e4 & 2) ? 8 : 0);
                int idx = s * RS1 + u;
                __half hh = __float2half_rn(h);
                __half hl = __float2half_rn(h - __half2float(hh));
                h1hiW[idx] = hh;
                h1loW[idx] = hl;
                st16_rem_(rbase + A_H1HI + pw * 8704 + idx * 2, hh);
                st16_rem_(rbase + A_H1LO + pw * 8704 + idx * 2, hl);
            }
            arrive_rem_(rbase + A_MBH1);
        }
        __syncthreads();
        waitp_(sbase + A_MBH1, tt & 1);  // peer h1(t)

        // ---- L2: z2 = h1(t)@W2 + h2(t-1)@U2 + b2 (K=192 split 48x4) ----
        float C2[4][8];
        if (kh2 == 0) {
#pragma unroll
            for (int gg = 0; gg < 4; gg++)
#pragma unroll
                for (int e = 0; e < 8; e++) C2[gg][e] = b2v[gg * 2 + (e & 1)];
            gemm_part<3, 12>(C2, g_wfrag + SEC_L2, 0, 4 * rk + wl2, 8,
                             h1hiW, h1loW, RS1, g, t);
        } else {
#pragma unroll
            for (int gg = 0; gg < 4; gg++)
#pragma unroll
                for (int e = 0; e < 8; e++) C2[gg][e] = 0.0f;
            if (kh2 == 1) {
                gemm_part<3, 12>(C2, g_wfrag + SEC_L2, 3, 4 * rk + wl2, 8,
                                 h1hiW + 48, h1loW + 48, RS1, g, t);
            } else if (kh2 == 2) {
                gemm_part<2, 12>(C2, g_wfrag + SEC_L2, 6, 4 * rk + wl2, 8,
                                 h1hiW + 96, h1loW + 96, RS1, g, t);
                gemm_part<1, 12>(C2, g_wfrag + SEC_L2, 8, 4 * rk + wl2, 8,
                                 h2hiR, h2loR, RS2, g, t);
            } else {
                gemm_part<3, 12>(C2, g_wfrag + SEC_L2, 9, 4 * rk + wl2, 8,
                                 h2hiR + 16, h2loR + 16, RS2, g, t);
            }
#pragma unroll
            for (int gg = 0; gg < 4; gg++)
#pragma unroll
                for (int e = 0; e < 8; e++)
                    pb[(kh2 - 1) * 4096 + (gg * 8 + e) * 128 + wl2 * 32 + lane] = C2[gg][e];
        }
        __syncthreads();
        if (kh2 == 0) {
#pragma unroll
            for (int e = 0; e < 8; e++) {
                int e4 = e & 3, r = e >> 2;
                int pi = wl2 * 32 + lane;
                float zi = C2[0][e], zf = C2[1][e], zg = C2[2][e], zo = C2[3][e];
#pragma unroll
                for (int q = 0; q < 3; q++) {
                    zi += pb[q * 4096 + (0 * 8 + e) * 128 + pi];
                    zf += pb[q * 4096 + (1 * 8 + e) * 128 + pi];
                    zg += pb[q * 4096 + (2 * 8 + e) * 128 + pi];
                    zo += pb[q * 4096 + (3 * 8 + e) * 128 + pi];
                }
                float h = lstm_cell(zi, zf, zg, zo, c2[e]);
                int u = uL2 + (e4 & 1), s = r * 16 + g + ((e4 & 2) ? 8 : 0);
                int idx = s * RS2 + u;
                __half hh = __float2half_rn(h);
                __half hl = __float2half_rn(h - __half2float(hh));
                h2hiW[idx] = hh;
                h2loW[idx] = hl;
                st16_rem_(rbase + A_H2HI + pw * 4608 + idx * 2, hh);
                st16_rem_(rbase + A_H2LO + pw * 4608 + idx * 2, hl);
                if (tt == T_SEQ - 1) g_h2last[(b0 + s) * 64 + u] = h;
            }
            arrive_rem_(rbase + A_MBH2);
        }
        __syncthreads();  // pbuf free before next L1 dump
    }
    CLUSTER_SYNC_();
}

// ---------------------------------------------------------------------------
// Phase B: Repeat(h2last) -> LSTM3 -> LSTM4 -> Dense(1). Cluster 2, N-split.
// ---------------------------------------------------------------------------
__global__ void __launch_bounds__(512, 1) __cluster_dims__(2, 1, 1)
phaseB_kernel(const float* __restrict__ W3, const float* __restrict__ b3,
              const float* __restrict__ b4, const float* __restrict__ Wd,
              const float* __restrict__ bd, float* __restrict__ out) {
    extern __shared__ char smem[];
    const int tid = threadIdx.x;
    const int w = tid >> 5, lane = tid & 31, g = lane >> 2, t = lane & 3;
    const int wl = w & 7, kh = w >> 3;    // L4
    const int wl2 = w & 3, kh2 = w >> 2;  // L3
    uint rk;
    asm("mov.u32 %0, %%cluster_ctarank;" : "=r"(rk));
    const uint peer = 1u - rk;
    const int b0 = (blockIdx.x >> 1) * BT;

    float* h2s = (float*)(smem + B_H2S);
    float* pb  = (float*)(smem + B_PBUF);
    float* pd  = (float*)(smem + B_PD);
    float* pd2 = (float*)(smem + B_PD2);
    const uint sbase = sm32_(smem);
    uint rbase;
    asm("mapa.shared::cluster.u32 %0, %1, %2;" : "=r"(rbase) : "r"(sbase), "r"(peer));

    for (int i = tid; i < BT * 64; i += 512) {
        int b = i >> 6, k = i & 63;
        h2s[b * 66 + k] = g_h2last[(b0 + b) * 64 + k];
    }
    for (int i = tid; i < 13312; i += 512) ((uint*)smem)[i] = 0u;  // h buffers
    if (tid == 0) {
        mbar_init_(sbase + B_MBH3, 128);
        mbar_init_(sbase + B_MBH4, 256);
        mbar_init_(sbase + B_MBD, 32);
    }
    __syncthreads();

    const int uL4 = 64 * (int)rk + 8 * wl + 2 * t;
    const int uL3 = 32 * (int)rk + 8 * wl2 + 2 * t;

    float b4v[8], wd0, wd1;
#pragma unroll
    for (int gg = 0; gg < 4; gg++)
#pragma unroll
        for (int e1 = 0; e1 < 2; e1++)
            b4v[gg * 2 + e1] = b4[gg * 128 + uL4 + e1];
    wd0 = Wd[uL4];
    wd1 = Wd[uL4 + 1];
    const float bdv = bd[0];

    // zx3 = b3 + h2last@W3 (fp32 exact; only kh2==0 warps need it)
    float zx[4][8];
    if (kh2 == 0) {
#pragma unroll
        for (int gg = 0; gg < 4; gg++)
#pragma unroll
            for (int e = 0; e < 8; e++) zx[gg][e] = b3[gg * 64 + uL3 + (e & 1)];
        for (int k = 0; k < 64; k++) {
            float ha = h2s[g * 66 + k];
            float hb = h2s[(g + 8) * 66 + k];
            float hc = h2s[(16 + g) * 66 + k];
            float hd = h2s[(24 + g) * 66 + k];
#pragma unroll
            for (int gg = 0; gg < 4; gg++) {
                float w0 = W3[k * 256 + gg * 64 + uL3];
                float w1 = W3[k * 256 + gg * 64 + uL3 + 1];
                zx[gg][0] = fmaf(ha, w0, zx[gg][0]);
                zx[gg][1] = fmaf(ha, w1, zx[gg][1]);
                zx[gg][2] = fmaf(hb, w0, zx[gg][2]);
                zx[gg][3] = fmaf(hb, w1, zx[gg][3]);
                zx[gg][4] = fmaf(hc, w0, zx[gg][4]);
                zx[gg][5] = fmaf(hc, w1, zx[gg][5]);
                zx[gg][6] = fmaf(hd, w0, zx[gg][6]);
                zx[gg][7] = fmaf(hd, w1, zx[gg][7]);
            }
        }
    }
    CLUSTER_SYNC_();

    float c3[8], c4[8];
#pragma unroll
    for (int j = 0; j < 8; j++) { c3[j] = 0.0f; c4[j] = 0.0f; }

    for (int tt = 0; tt < T_SEQ; tt++) {
        const int pw = tt & 1, po = pw ^ 1;
        __half* h3hiR = (__half*)(smem + B_H3HI + po * 4608);
        __half* h3loR = (__half*)(smem + B_H3LO + po * 4608);
        __half* h3hiW = (__half*)(smem + B_H3HI + pw * 4608);
        __half* h3loW = (__half*)(smem + B_H3LO + pw * 4608);
        __half* h4hiR = (__half*)(smem + B_H4HI + po * 8704);
        __half* h4loR = (__half*)(smem + B_H4LO + po * 8704);
        __half* h4hiW = (__half*)(smem + B_H4HI + pw * 8704);
        __half* h4loW = (__half*)(smem + B_H4LO + pw * 8704);

        if (tt > 0) {
            waitp_(sbase + B_MBH3, (tt - 1) & 1);
            waitp_(sbase + B_MBH4, (tt - 1) & 1);
        }

        // ---- L3: z3 = zx3 + h3(t-1)@U3 (K=64 split 16x4) ----
        float C3[4][8];
        if (kh2 == 0) {
#pragma unroll
            for (int gg = 0; gg < 4; gg++)
#pragma unroll
                for (int e = 0; e < 8; e++) C3[gg][e] = zx[gg][e];
            gemm_part<1, 4>(C3, g_wfrag + SEC_L3, 0, 4 * rk + wl2, 8,
                            h3hiR, h3loR, RS2, g, t);
        } else {
#pragma unroll
            for (int gg = 0; gg < 4; gg++)
#pragma unroll
                for (int e = 0; e < 8; e++) C3[gg][e] = 0.0f;
            gemm_part<1, 4>(C3, g_wfrag + SEC_L3, kh2, 4 * rk + wl2, 8,
                            h3hiR + 16 * kh2, h3loR + 16 * kh2, RS2, g, t);
#pragma unroll
            for (int gg = 0; gg < 4; gg++)
#pragma unroll
                for (int e = 0; e < 8; e++)
                    pb[(kh2 - 1) * 4096 + (gg * 8 + e) * 128 + wl2 * 32 + lane] = C3[gg][e];
        }
        __syncthreads();
        if (kh2 == 0) {
#pragma unroll
            for (int e = 0; e < 8; e++) {
                int e4 = e & 3, r = e >> 2;
                int pi = wl2 * 32 + lane;
                float zi = C3[0][e], zf = C3[1][e], zg = C3[2][e], zo = C3[3][e];
#pragma unroll
                for (int q = 0; q < 3; q++) {
                    zi += pb[q * 4096 + (0 * 8 + e) * 128 + pi];
                    zf += pb[q * 4096 + (1 * 8 + e) * 128 + pi];
                    zg += pb[q * 4096 + (2 * 8 + e) * 128 + pi];
                    zo += pb[q * 4096 + (3 * 8 + e) * 128 + pi];
                }
                float h = lstm_cell(zi, zf, zg, zo, c3[e]);
                int u = uL3 + (e4 & 1), s = r * 16 + g + ((e4 & 2) ? 8 : 0);
                int idx = s * RS2 + u;
                __half hh = __float2half_rn(h);
                __half hl = __float2half_rn(h - __half2float(hh));
                h3hiW[idx] = hh;
                h3loW[idx] = hl;
                st16_rem_(rbase + B_H3HI + pw * 4608 + idx * 2, hh);
                st16_rem_(rbase + B_H3LO + pw * 4608 + idx * 2, hl);
            }
            arrive_rem_(rbase + B_MBH3);
        }
        __syncthreads();
        waitp_(sbase + B_MBH3, tt & 1);  // peer h3(t)

        // ---- L4: z4 = h3(t)@W4 + h4(t-1)@U4 + b4 (K=192 split 96/96) ----
        float C4[4][8];
        if (kh == 0) {
#pragma unroll
            for (int gg = 0; gg < 4; gg++)
#pragma unroll
                for (int e = 0; e < 8; e++) C4[gg][e] = b4v[gg * 2 + (e & 1)];
            gemm_part<4, 12>(C4, g_wfrag + SEC_L4, 0, 8 * rk + wl, 16,
                             h3hiW, h3loW, RS2, g, t);
            gemm_part<2, 12>(C4, g_wfrag + SEC_L4, 4, 8 * rk + wl, 16,
                             h4hiR, h4loR, RS1, g, t);
        } else {
#pragma unroll
            for (int gg = 0; gg < 4; gg++)
#pragma unroll
                for (int e = 0; e < 8; e++) C4[gg][e] = 0.0f;
            gemm_part<6, 12>(C4, g_wfrag + SEC_L4, 6, 8 * rk + wl, 16,
                             h4hiR + 32, h4loR + 32, RS1, g, t);
#pragma unroll
            for (int gg = 0; gg < 4; gg++)
#pragma unroll
                for (int e = 0; e < 8; e++)
                    pb[(gg * 8 + e) * 256 + wl * 32 + lane] = C4[gg][e];
        }
        __syncthreads();
        if (kh == 0) {
            float p[4] = {0.0f, 0.0f, 0.0f, 0.0f};
#pragma unroll
            for (int e = 0; e < 8; e++) {
                int e4 = e & 3, r = e >> 2;
                int pi = wl * 32 + lane;
                float zi = C4[0][e] + pb[(0 * 8 + e) * 256 + pi];
                float zf = C4[1][e] + pb[(1 * 8 + e) * 256 + pi];
                float zg = C4[2][e] + pb[(2 * 8 + e) * 256 + pi];
                float zo = C4[3][e] + pb[(3 * 8 + e) * 256 + pi];
                float h = lstm_cell(zi, zf, zg, zo, c4[e]);
                int u = uL4 + (e4 & 1), s = r * 16 + g + ((e4 & 2) ? 8 : 0);
                int idx = s * RS1 + u;
                __half hh = __float2half_rn(h);
                __half hl = __float2half_rn(h - __half2float(hh));
                h4hiW[idx] = hh;
                h4loW[idx] = hl;
                st16_rem_(rbase + B_H4HI + pw * 8704 + idx * 2, hh);
                st16_rem_(rbase + B_H4LO + pw * 8704 + idx * 2, hl);
                float wv = (e4 & 1) ? wd1 : wd0;
                int pidx = r * 2 + ((e4 & 2) ? 1 : 0);
                p[pidx] = fmaf(h, wv, p[pidx]);
            }
            arrive_rem_(rbase + B_MBH4);
#pragma unroll
            for (int q = 0; q < 4; q++) {
                p[q] += __shfl_xor_sync(0xffffffffu, p[q], 1);
                p[q] += __shfl_xor_sync(0xffffffffu, p[q], 2);
            }
            if (t == 0) {
                pd[wl * 32 + g]      = p[0];
                pd[wl * 32 + 8 + g]  = p[1];
                pd[wl * 32 + 16 + g] = p[2];
                pd[wl * 32 + 24 + g] = p[3];
            }
        }
        __syncthreads();
        if (tid < 32) {
            float pr_ = 0.0f;
#pragma unroll
            for (int q = 0; q < 8; q++) pr_ += pd[q * 32 + tid];
            if (rk == 1) {
                st32_rem_(rbase + B_PD2 + tid * 4, pr_);
                arrive_rem_(rbase + B_MBD);
            } else {
                waitp_(sbase + B_MBD, tt & 1);
                out[(b0 + tid) * T_SEQ + tt] = pr_ + pd2[tid] + bdv;
            }
        }
    }
    CLUSTER_SYNC_();
}

// ---------------------------------------------------------------------------
extern "C" void kernel_launch(void* const* d_in, const int* in_sizes, int n_in,
                              void* d_out, int out_size) {
    const float* x  = (const float*)d_in[0];
    const float* W1 = (const float*)d_in[1];
    const float* U1 = (const float*)d_in[2];
    const float* b1 = (const float*)d_in[3];
    const float* W2 = (const float*)d_in[4];
    const float* U2 = (const float*)d_in[5];
    const float* b2 = (const float*)d_in[6];
    const float* W3 = (const float*)d_in[7];
    const float* U3 = (const float*)d_in[8];
    const float* b3 = (const float*)d_in[9];
    const float* W4 = (const float*)d_in[10];
    const float* U4 = (const float*)d_in[11];
    const float* b4 = (const float*)d_in[12];
    const float* Wd = (const float*)d_in[13];
    const float* bd = (const float*)d_in[14];
    float* out = (float*)d_out;

    cudaFuncSetAttribute(phaseA_kernel,
                         cudaFuncAttributeMaxDynamicSharedMemorySize, SMEMA_BYTES);
    cudaFuncSetAttribute(phaseB_kernel,
                         cudaFuncAttributeMaxDynamicSharedMemorySize, SMEMB_BYTES);

    pack_kernel<<<224, 256>>>(U1, W2, U2, U3, W4, U4);
    phaseA_kernel<<<NCTAS, 512, SMEMA_BYTES>>>(x, W1, b1, b2);
    phaseB_kernel<<<NCTAS, 512, SMEMB_BYTES>>>(W3, b3, b4, Wd, bd, out);
}